// round 2
// baseline (speedup 1.0000x reference)
#include <cuda_runtime.h>
#include <cstdint>

// ============================================================================
// AmbientSphericalBrownianMotion — Stratonovich-Heun BM on S^2, N=4.2M pts,
// 100 steps. Bit-reproduces JAX threefry2x32 (partitionable: bits1^bits2)
// + XLA erfinv.
// ============================================================================

#define MAX_STEPS 4096
__device__ uint2 g_step_keys[MAX_STEPS];

__device__ __forceinline__ uint32_t rotl32(uint32_t v, int r) {
    return __funnelshift_l(v, v, r);
}

__device__ __forceinline__ void tf_round(uint32_t& x0, uint32_t& x1, int r) {
    x0 += x1;
    x1 = rotl32(x1, r);
    x1 ^= x0;
}

__device__ __forceinline__ void tf_group_a(uint32_t& x0, uint32_t& x1) {
    tf_round(x0, x1, 13); tf_round(x0, x1, 15);
    tf_round(x0, x1, 26); tf_round(x0, x1, 6);
}
__device__ __forceinline__ void tf_group_b(uint32_t& x0, uint32_t& x1) {
    tf_round(x0, x1, 17); tf_round(x0, x1, 29);
    tf_round(x0, x1, 16); tf_round(x0, x1, 24);
}

// Full threefry2x32, 20 rounds, JAX key schedule. Returns both output words.
__device__ __forceinline__ uint2 threefry2x32(uint32_t k0, uint32_t k1,
                                              uint32_t c0, uint32_t c1) {
    const uint32_t k2 = k0 ^ k1 ^ 0x1BD11BDAu;
    uint32_t x0 = c0 + k0;
    uint32_t x1 = c1 + k1;
    tf_group_a(x0, x1); x0 += k1; x1 += k2 + 1u;
    tf_group_b(x0, x1); x0 += k2; x1 += k0 + 2u;
    tf_group_a(x0, x1); x0 += k0; x1 += k1 + 3u;
    tf_group_b(x0, x1); x0 += k1; x1 += k2 + 4u;
    tf_group_a(x0, x1);
    return make_uint2(x0 + k2, x1 + k0 + 5u);
}

// JAX partitionable random_bits(32): XOR of the two threefry output lanes.
// Counter is the flat 64-bit iota (hi word 0 for our sizes): c0=0, c1=e.
__device__ __forceinline__ uint32_t threefry2x32_xor(uint32_t k0, uint32_t k1,
                                                     uint32_t k2, uint32_t c1) {
    uint32_t x0 = k0;          // c0 = 0
    uint32_t x1 = c1 + k1;
    tf_group_a(x0, x1); x0 += k1; x1 += k2 + 1u;
    tf_group_b(x0, x1); x0 += k2; x1 += k0 + 2u;
    tf_group_a(x0, x1); x0 += k0; x1 += k1 + 3u;
    tf_group_b(x0, x1); x0 += k1; x1 += k2 + 4u;
    tf_group_a(x0, x1);
    return (x0 + k2) ^ (x1 + k0 + 5u);
}

// XLA ErfInv32 polynomial (Giles), matching lax.erf_inv lowering for f32.
__device__ __forceinline__ float xla_erfinv(float x) {
    float w = -log1pf(-(x * x));
    float p;
    if (w < 5.0f) {
        w = w - 2.5f;
        p =            2.81022636e-08f;
        p = fmaf(p, w, 3.43273939e-07f);
        p = fmaf(p, w, -3.5233877e-06f);
        p = fmaf(p, w, -4.39150654e-06f);
        p = fmaf(p, w, 0.00021858087f);
        p = fmaf(p, w, -0.00125372503f);
        p = fmaf(p, w, -0.00417768164f);
        p = fmaf(p, w, 0.246640727f);
        p = fmaf(p, w, 1.50140941f);
    } else {
        w = sqrtf(w) - 3.0f;
        p =            -0.000200214257f;
        p = fmaf(p, w, 0.000100950558f);
        p = fmaf(p, w, 0.00134934322f);
        p = fmaf(p, w, -0.00367342844f);
        p = fmaf(p, w, 0.00573950773f);
        p = fmaf(p, w, -0.0076224613f);
        p = fmaf(p, w, 0.00943887047f);
        p = fmaf(p, w, 1.00167406f);
        p = fmaf(p, w, 2.83297682f);
    }
    return p * x;
}

// uniform(lo=nextafter(-1,0), hi=1) -> sqrt(2)*erfinv(u), JAX/XLA semantics.
__device__ __forceinline__ float jax_normal_from_bits(uint32_t bits) {
    const float LO = -0.99999994f;  // 0xBF7FFFFF
    float f = __uint_as_float((bits >> 9) | 0x3f800000u) - 1.0f;
    float u = fmaxf(LO, fmaf(f, 2.0f, LO));
    return 1.4142135381698608f * xla_erfinv(u);
}

// ((a0b0 + a1b1) + a2b2), no FMA contraction (XLA reduce order)
__device__ __forceinline__ float dot3(float a0, float a1, float a2,
                                      float b0, float b1, float b2) {
    return __fadd_rn(__fadd_rn(__fmul_rn(a0, b0), __fmul_rn(a1, b1)),
                     __fmul_rn(a2, b2));
}

// ---------------------------------------------------------------------------
// Pre-kernel: per-step folded keys.  fold_in(key(1), i) = threefry((0,1),(0,i))
// ---------------------------------------------------------------------------
__global__ void keys_kernel(const int* __restrict__ steps_ptr) {
    int steps = *steps_ptr;
    if (steps > MAX_STEPS) steps = MAX_STEPS;
    for (int s = threadIdx.x; s < steps; s += blockDim.x) {
        g_step_keys[s] = threefry2x32(0u, 1u, 0u, (uint32_t)s);
    }
}

// ---------------------------------------------------------------------------
// Main kernel: one thread per point, full trajectory in registers.
// ---------------------------------------------------------------------------
__global__ void __launch_bounds__(256)
sbm_kernel(const float* __restrict__ xin,
           const int* __restrict__ t_ptr,
           const int* __restrict__ steps_ptr,
           float* __restrict__ out, int n) {
    int i = blockIdx.x * blockDim.x + threadIdx.x;
    if (i >= n) return;

    const int steps = *steps_ptr;
    const float dt = (float)(*t_ptr) / (float)steps;
    const float sqrt_dt = sqrtf(dt);

    float x0 = xin[3 * i + 0];
    float x1 = xin[3 * i + 1];
    float x2 = xin[3 * i + 2];

    const uint32_t base = 3u * (uint32_t)i;

    for (int s = 0; s < steps; ++s) {
        const uint2 fk = g_step_keys[s];
        const uint32_t fk2 = fk.x ^ fk.y ^ 0x1BD11BDAu;

        // inc = normal * sqrt(dt), per coordinate (elements base, base+1, base+2)
        float v0, v1, v2;
        {
            uint32_t b0 = threefry2x32_xor(fk.x, fk.y, fk2, base + 0u);
            uint32_t b1 = threefry2x32_xor(fk.x, fk.y, fk2, base + 1u);
            uint32_t b2 = threefry2x32_xor(fk.x, fk.y, fk2, base + 2u);
            v0 = __fmul_rn(jax_normal_from_bits(b0), sqrt_dt);
            v1 = __fmul_rn(jax_normal_from_bits(b1), sqrt_dt);
            v2 = __fmul_rn(jax_normal_from_bits(b2), sqrt_dt);
        }

        // g0 = v - (x.v / x.x) * x
        float d_xv = dot3(x0, x1, x2, v0, v1, v2);
        float d_xx = dot3(x0, x1, x2, x0, x1, x2);
        float r0 = __fdiv_rn(d_xv, d_xx);
        float g00 = __fsub_rn(v0, __fmul_rn(r0, x0));
        float g01 = __fsub_rn(v1, __fmul_rn(r0, x1));
        float g02 = __fsub_rn(v2, __fmul_rn(r0, x2));

        // y' = x + g0
        float y0 = __fadd_rn(x0, g00);
        float y1 = __fadd_rn(x1, g01);
        float y2 = __fadd_rn(x2, g02);

        // g' = v - (y'.v / y'.y') * y'
        float d_yv = dot3(y0, y1, y2, v0, v1, v2);
        float d_yy = dot3(y0, y1, y2, y0, y1, y2);
        float r1 = __fdiv_rn(d_yv, d_yy);
        float gp0 = __fsub_rn(v0, __fmul_rn(r1, y0));
        float gp1 = __fsub_rn(v1, __fmul_rn(r1, y1));
        float gp2 = __fsub_rn(v2, __fmul_rn(r1, y2));

        // y1 = x + 0.5*(g0 + g')
        float z0 = __fadd_rn(x0, __fmul_rn(0.5f, __fadd_rn(g00, gp0)));
        float z1 = __fadd_rn(x1, __fmul_rn(0.5f, __fadd_rn(g01, gp1)));
        float z2 = __fadd_rn(x2, __fmul_rn(0.5f, __fadd_rn(g02, gp2)));

        // x = y1 / ||y1||
        float nrm = sqrtf(dot3(z0, z1, z2, z0, z1, z2));
        x0 = __fdiv_rn(z0, nrm);
        x1 = __fdiv_rn(z1, nrm);
        x2 = __fdiv_rn(z2, nrm);
    }

    out[3 * i + 0] = x0;
    out[3 * i + 1] = x1;
    out[3 * i + 2] = x2;
}

// ---------------------------------------------------------------------------
extern "C" void kernel_launch(void* const* d_in, const int* in_sizes, int n_in,
                              void* d_out, int out_size) {
    const float* x     = (const float*)d_in[0];
    const int*   t     = (const int*)d_in[1];
    const int*   steps = (const int*)d_in[2];
    const int n = in_sizes[0] / 3;

    keys_kernel<<<1, 256>>>(steps);

    const int threads = 256;
    const int blocks = (n + threads - 1) / threads;
    sbm_kernel<<<blocks, threads>>>(x, t, steps, (float*)d_out, n);
}

// round 3
// speedup vs baseline: 1.3215x; 1.3215x over previous
#include <cuda_runtime.h>
#include <cstdint>

// ============================================================================
// AmbientSphericalBrownianMotion — Stratonovich-Heun BM on S^2, N=4.2M pts,
// 100 steps. Bit-exact JAX threefry2x32 random bits (partitionable:
// bits0 ^ bits1); fast-math transcendentals (dynamics are contractive,
// measured rel_err headroom ~3000x vs threshold).
// ============================================================================

#define MAX_STEPS 4096
__device__ uint4 g_step_keys[MAX_STEPS];   // (k0, k1, k2, pad)

__device__ __forceinline__ uint32_t rotl32(uint32_t v, int r) {
    return __funnelshift_l(v, v, r);
}

__device__ __forceinline__ void tf_round(uint32_t& x0, uint32_t& x1, int r) {
    x0 += x1;
    x1 = rotl32(x1, r);
    x1 ^= x0;
}

__device__ __forceinline__ void tf_group_a(uint32_t& x0, uint32_t& x1) {
    tf_round(x0, x1, 13); tf_round(x0, x1, 15);
    tf_round(x0, x1, 26); tf_round(x0, x1, 6);
}
__device__ __forceinline__ void tf_group_b(uint32_t& x0, uint32_t& x1) {
    tf_round(x0, x1, 17); tf_round(x0, x1, 29);
    tf_round(x0, x1, 16); tf_round(x0, x1, 24);
}

// Full threefry2x32 (for key folding only).
__device__ __forceinline__ uint2 threefry2x32(uint32_t k0, uint32_t k1,
                                              uint32_t c0, uint32_t c1) {
    const uint32_t k2 = k0 ^ k1 ^ 0x1BD11BDAu;
    uint32_t x0 = c0 + k0;
    uint32_t x1 = c1 + k1;
    tf_group_a(x0, x1); x0 += k1; x1 += k2 + 1u;
    tf_group_b(x0, x1); x0 += k2; x1 += k0 + 2u;
    tf_group_a(x0, x1); x0 += k0; x1 += k1 + 3u;
    tf_group_b(x0, x1); x0 += k1; x1 += k2 + 4u;
    tf_group_a(x0, x1);
    return make_uint2(x0 + k2, x1 + k0 + 5u);
}

// JAX partitionable random_bits(32): XOR of the two output lanes.
// c0 = 0 (flat index < 2^32). x1init = c1 + k1 passed in pre-added.
__device__ __forceinline__ uint32_t threefry2x32_xor(uint32_t k0, uint32_t k1,
                                                     uint32_t k2, uint32_t x1init) {
    uint32_t x0 = k0;
    uint32_t x1 = x1init;
    tf_group_a(x0, x1); x0 += k1; x1 += k2 + 1u;
    tf_group_b(x0, x1); x0 += k2; x1 += k0 + 2u;
    tf_group_a(x0, x1); x0 += k0; x1 += k1 + 3u;
    tf_group_b(x0, x1); x0 += k1; x1 += k2 + 4u;
    tf_group_a(x0, x1);
    return (x0 + k2) ^ (x1 + k0 + 5u);
}

// ---- fast-math primitives (guaranteed MUFU regardless of compile flags) ----
__device__ __forceinline__ float lg2_fast(float x) {
    float r; asm("lg2.approx.f32 %0, %1;" : "=f"(r) : "f"(x)); return r;
}
__device__ __forceinline__ float rcp_fast(float x) {
    float r; asm("rcp.approx.f32 %0, %1;" : "=f"(r) : "f"(x)); return r;
}
__device__ __forceinline__ float rsqrt_fast(float x) {
    float r; asm("rsqrt.approx.f32 %0, %1;" : "=f"(r) : "f"(x)); return r;
}

// Giles erfinv polynomial on w = -ln(1 - u^2); returns p with erfinv = p*u.
__device__ __forceinline__ float erfinv_p(float u) {
    // w = -ln(1-u^2) = lg2(fma(-u,u,1)) * (-ln2)
    float w = lg2_fast(fmaf(-u, u, 1.0f)) * (-0.6931471805599453f);
    float p;
    if (w < 5.0f) {
        w = w - 2.5f;
        p =            2.81022636e-08f;
        p = fmaf(p, w, 3.43273939e-07f);
        p = fmaf(p, w, -3.5233877e-06f);
        p = fmaf(p, w, -4.39150654e-06f);
        p = fmaf(p, w, 0.00021858087f);
        p = fmaf(p, w, -0.00125372503f);
        p = fmaf(p, w, -0.00417768164f);
        p = fmaf(p, w, 0.246640727f);
        p = fmaf(p, w, 1.50140941f);
    } else {
        w = sqrtf(w) - 3.0f;
        p =            -0.000200214257f;
        p = fmaf(p, w, 0.000100950558f);
        p = fmaf(p, w, 0.00134934322f);
        p = fmaf(p, w, -0.00367342844f);
        p = fmaf(p, w, 0.00573950773f);
        p = fmaf(p, w, -0.0076224613f);
        p = fmaf(p, w, 0.00943887047f);
        p = fmaf(p, w, 1.00167406f);
        p = fmaf(p, w, 2.83297682f);
    }
    return p;
}

// bits -> uniform(nextafter(-1,0), 1) -> normal * scale  (scale = sqrt2*sqrt_dt)
__device__ __forceinline__ float normal_from_bits(uint32_t bits, float scale) {
    const float LO = -0.99999994f;  // 0xBF7FFFFF
    float f = __uint_as_float((bits >> 9) | 0x3f800000u) - 1.0f;
    float u = fmaxf(LO, fmaf(f, 2.0f, LO));
    return (erfinv_p(u) * u) * scale;
}

// FMA-fused 3-dot
__device__ __forceinline__ float dot3(float a0, float a1, float a2,
                                      float b0, float b1, float b2) {
    return fmaf(a2, b2, fmaf(a1, b1, a0 * b0));
}

// ---------------------------------------------------------------------------
// Pre-kernel: per-step folded keys.  fold_in(key(1), i) = threefry((0,1),(0,i))
// ---------------------------------------------------------------------------
__global__ void keys_kernel(const int* __restrict__ steps_ptr) {
    int steps = *steps_ptr;
    if (steps > MAX_STEPS) steps = MAX_STEPS;
    for (int s = threadIdx.x; s < steps; s += blockDim.x) {
        uint2 k = threefry2x32(0u, 1u, 0u, (uint32_t)s);
        g_step_keys[s] = make_uint4(k.x, k.y, k.x ^ k.y ^ 0x1BD11BDAu, 0u);
    }
}

// ---------------------------------------------------------------------------
// Main kernel: one thread per point, full trajectory in registers.
// ---------------------------------------------------------------------------
__global__ void __launch_bounds__(256)
sbm_kernel(const float* __restrict__ xin,
           const int* __restrict__ t_ptr,
           const int* __restrict__ steps_ptr,
           float* __restrict__ out, int n) {
    int i = blockIdx.x * blockDim.x + threadIdx.x;
    if (i >= n) return;

    const int steps = *steps_ptr;
    const float dt = (float)(*t_ptr) / (float)steps;
    const float scale = 1.4142135381698608f * sqrtf(dt);   // sqrt2 * sqrt_dt

    float x0 = xin[3 * i + 0];
    float x1 = xin[3 * i + 1];
    float x2 = xin[3 * i + 2];

    const uint32_t base = 3u * (uint32_t)i;

    for (int s = 0; s < steps; ++s) {
        const uint4 fk = g_step_keys[s];   // k0, k1, k2

        // three fresh random bits for this (point, step)
        const uint32_t c1k = base + fk.y;  // counter + k1, shared init
        uint32_t b0 = threefry2x32_xor(fk.x, fk.y, fk.z, c1k);
        uint32_t b1 = threefry2x32_xor(fk.x, fk.y, fk.z, c1k + 1u);
        uint32_t b2 = threefry2x32_xor(fk.x, fk.y, fk.z, c1k + 2u);

        float v0 = normal_from_bits(b0, scale);
        float v1 = normal_from_bits(b1, scale);
        float v2 = normal_from_bits(b2, scale);

        // g0 = v - (x.v / x.x) * x
        float d_xv = dot3(x0, x1, x2, v0, v1, v2);
        float d_xx = dot3(x0, x1, x2, x0, x1, x2);
        float r0 = d_xv * rcp_fast(d_xx);
        float g00 = fmaf(-r0, x0, v0);
        float g01 = fmaf(-r0, x1, v1);
        float g02 = fmaf(-r0, x2, v2);

        // y' = x + g0
        float y0 = x0 + g00;
        float y1 = x1 + g01;
        float y2 = x2 + g02;

        // g' = v - (y'.v / y'.y') * y'
        float d_yv = dot3(y0, y1, y2, v0, v1, v2);
        float d_yy = dot3(y0, y1, y2, y0, y1, y2);
        float r1 = d_yv * rcp_fast(d_yy);
        float gp0 = fmaf(-r1, y0, v0);
        float gp1 = fmaf(-r1, y1, v1);
        float gp2 = fmaf(-r1, y2, v2);

        // z = x + 0.5*(g0 + g')
        float z0 = fmaf(0.5f, g00 + gp0, x0);
        float z1 = fmaf(0.5f, g01 + gp1, x1);
        float z2 = fmaf(0.5f, g02 + gp2, x2);

        // x = z / ||z||
        float inv = rsqrt_fast(dot3(z0, z1, z2, z0, z1, z2));
        x0 = z0 * inv;
        x1 = z1 * inv;
        x2 = z2 * inv;
    }

    out[3 * i + 0] = x0;
    out[3 * i + 1] = x1;
    out[3 * i + 2] = x2;
}

// ---------------------------------------------------------------------------
extern "C" void kernel_launch(void* const* d_in, const int* in_sizes, int n_in,
                              void* d_out, int out_size) {
    const float* x     = (const float*)d_in[0];
    const int*   t     = (const int*)d_in[1];
    const int*   steps = (const int*)d_in[2];
    const int n = in_sizes[0] / 3;

    keys_kernel<<<1, 256>>>(steps);

    const int threads = 256;
    const int blocks = (n + threads - 1) / threads;
    sbm_kernel<<<blocks, threads>>>(x, t, steps, (float*)d_out, n);
}

// round 4
// speedup vs baseline: 1.3663x; 1.0340x over previous
#include <cuda_runtime.h>
#include <cstdint>

// ============================================================================
// AmbientSphericalBrownianMotion — Stratonovich-Heun BM on S^2, N=4.2M pts,
// 100 steps. Bit-exact JAX threefry2x32 random bits (partitionable:
// bits0 ^ bits1). Pipe-balanced: threefry adds forced onto IMAD (fma pipe)
// via opaque multiplier; SHF/LOP3 stay on alu pipe. I2F-based uniform,
// lg2-domain erfinv, closed-form (alpha*x + beta*v) Heun step.
// ============================================================================

#define MAX_STEPS 4096
struct __align__(16) StepKey {
    uint4 a;   // k0, k1, k2, k2+1
    uint4 b;   // k0+2, k1+3, k2+4, k0+5
};
__device__ StepKey g_step_keys[MAX_STEPS];

__device__ __forceinline__ uint32_t rotl32(uint32_t v, int r) {
    return __funnelshift_l(v, v, r);
}

// add via IMAD (fma pipe): d = a*one + c, with `one` runtime-opaque == 1
__device__ __forceinline__ uint32_t imad1(uint32_t a, uint32_t one, uint32_t c) {
    uint32_t d;
    asm("mad.lo.u32 %0, %1, %2, %3;" : "=r"(d) : "r"(a), "r"(one), "r"(c));
    return d;
}

// threefry round, add on fma pipe; rot+xor on alu pipe
__device__ __forceinline__ void tfr(uint32_t& x0, uint32_t& x1, int r, uint32_t one) {
    x0 = imad1(x0, one, x1);
    x1 = rotl32(x1, r) ^ x0;
}

__device__ __forceinline__ void grpA(uint32_t& x0, uint32_t& x1, uint32_t one) {
    tfr(x0, x1, 13, one); tfr(x0, x1, 15, one);
    tfr(x0, x1, 26, one); tfr(x0, x1, 6,  one);
}
__device__ __forceinline__ void grpB(uint32_t& x0, uint32_t& x1, uint32_t one) {
    tfr(x0, x1, 17, one); tfr(x0, x1, 29, one);
    tfr(x0, x1, 16, one); tfr(x0, x1, 24, one);
}

// JAX partitionable random_bits(32): bits0 ^ bits1, with sign-flip constant
// folded into the final 3-input LOP3 (for the I2F uniform path).
__device__ __forceinline__ int32_t tf_sbits(const StepKey& k, uint32_t x1init,
                                            uint32_t one) {
    uint32_t x0 = k.a.x;   // c0 = 0, so x0 = k0
    uint32_t x1 = x1init;  // c1 + k1, pre-added by caller
    grpA(x0, x1, one); x0 = imad1(x0, one, k.a.y); x1 += k.a.w;  // +k1, +(k2+1)
    grpB(x0, x1, one); x0 = imad1(x0, one, k.a.z); x1 += k.b.x;  // +k2, +(k0+2)
    grpA(x0, x1, one); x0 = imad1(x0, one, k.a.x); x1 += k.b.y;  // +k0, +(k1+3)
    grpB(x0, x1, one); x0 = imad1(x0, one, k.a.y); x1 += k.b.z;  // +k1, +(k2+4)
    grpA(x0, x1, one);
    return (int32_t)((x0 + k.a.z) ^ (x1 + k.b.w) ^ 0x80000000u);
}

// ---- fast-math primitives ----
__device__ __forceinline__ float lg2_fast(float x) {
    float r; asm("lg2.approx.f32 %0, %1;" : "=f"(r) : "f"(x)); return r;
}
__device__ __forceinline__ float rcp_fast(float x) {
    float r; asm("rcp.approx.f32 %0, %1;" : "=f"(r) : "f"(x)); return r;
}
__device__ __forceinline__ float rsqrt_fast(float x) {
    float r; asm("rsqrt.approx.f32 %0, %1;" : "=f"(r) : "f"(x)); return r;
}
__device__ __forceinline__ float sqrt_fast(float x) {
    float r; asm("sqrt.approx.f32 %0, %1;" : "=f"(r) : "f"(x)); return r;
}

// signed bits -> uniform(-1,1) -> sqrt2*erfinv(u)*sqrt_dt  (scale = sqrt2*sqrt_dt)
// Giles polynomial evaluated with the log kept in lg2 domain.
__device__ __forceinline__ float normal_from_sbits(int32_t sb, float scale) {
    float u  = __int2float_rn(sb) * 4.6566128730773926e-10f;   // 2^-31
    float us = u * scale;
    float L  = lg2_fast(fmaf(-u, u, 1.0f));     // log2(1-u^2) <= 0
    L = fmaxf(L, -23.0058f);                    // clamp |u|->1 corner (w<=15.9424)
    float p;
    if (L > -7.2134752f) {                      // w < 5
        float w = fmaf(L, -0.69314718f, -2.5f); // w - 2.5
        p =            2.81022636e-08f;
        p = fmaf(p, w, 3.43273939e-07f);
        p = fmaf(p, w, -3.5233877e-06f);
        p = fmaf(p, w, -4.39150654e-06f);
        p = fmaf(p, w, 0.00021858087f);
        p = fmaf(p, w, -0.00125372503f);
        p = fmaf(p, w, -0.00417768164f);
        p = fmaf(p, w, 0.246640727f);
        p = fmaf(p, w, 1.50140941f);
    } else {
        float w = sqrt_fast(L * -0.69314718f) - 3.0f;
        p =            -0.000200214257f;
        p = fmaf(p, w, 0.000100950558f);
        p = fmaf(p, w, 0.00134934322f);
        p = fmaf(p, w, -0.00367342844f);
        p = fmaf(p, w, 0.00573950773f);
        p = fmaf(p, w, -0.0076224613f);
        p = fmaf(p, w, 0.00943887047f);
        p = fmaf(p, w, 1.00167406f);
        p = fmaf(p, w, 2.83297682f);
    }
    return p * us;
}

__device__ __forceinline__ float dot3(float a0, float a1, float a2,
                                      float b0, float b1, float b2) {
    return fmaf(a2, b2, fmaf(a1, b1, a0 * b0));
}

// ---------------------------------------------------------------------------
// Pre-kernel: per-step folded keys + precomputed injection constants.
//   fold_in(key(1), s) = threefry((0,1),(0,s))
// ---------------------------------------------------------------------------
__device__ __forceinline__ void tfr_p(uint32_t& x0, uint32_t& x1, int r) {
    x0 += x1; x1 = rotl32(x1, r) ^ x0;
}
__global__ void keys_kernel(const int* __restrict__ steps_ptr) {
    int steps = *steps_ptr;
    if (steps > MAX_STEPS) steps = MAX_STEPS;
    for (int s = threadIdx.x; s < steps; s += blockDim.x) {
        const uint32_t k0 = 0u, k1 = 1u;
        const uint32_t k2 = k0 ^ k1 ^ 0x1BD11BDAu;
        uint32_t x0 = k0, x1 = (uint32_t)s + k1;
        tfr_p(x0,x1,13); tfr_p(x0,x1,15); tfr_p(x0,x1,26); tfr_p(x0,x1,6);
        x0 += k1; x1 += k2 + 1u;
        tfr_p(x0,x1,17); tfr_p(x0,x1,29); tfr_p(x0,x1,16); tfr_p(x0,x1,24);
        x0 += k2; x1 += k0 + 2u;
        tfr_p(x0,x1,13); tfr_p(x0,x1,15); tfr_p(x0,x1,26); tfr_p(x0,x1,6);
        x0 += k0; x1 += k1 + 3u;
        tfr_p(x0,x1,17); tfr_p(x0,x1,29); tfr_p(x0,x1,16); tfr_p(x0,x1,24);
        x0 += k1; x1 += k2 + 4u;
        tfr_p(x0,x1,13); tfr_p(x0,x1,15); tfr_p(x0,x1,26); tfr_p(x0,x1,6);
        uint32_t fk0 = x0 + k2;
        uint32_t fk1 = x1 + k0 + 5u;
        uint32_t fk2 = fk0 ^ fk1 ^ 0x1BD11BDAu;
        StepKey sk;
        sk.a = make_uint4(fk0, fk1, fk2, fk2 + 1u);
        sk.b = make_uint4(fk0 + 2u, fk1 + 3u, fk2 + 4u, fk0 + 5u);
        g_step_keys[s] = sk;
    }
}

// ---------------------------------------------------------------------------
// Main kernel: one thread per point, full trajectory in registers.
// ---------------------------------------------------------------------------
__global__ void __launch_bounds__(256)
sbm_kernel(const float* __restrict__ xin,
           const int* __restrict__ t_ptr,
           const int* __restrict__ steps_ptr,
           float* __restrict__ out, int n) {
    int i = blockIdx.x * blockDim.x + threadIdx.x;
    if (i >= n) return;

    const int steps = *steps_ptr;
    const float dt = (float)(*t_ptr) / (float)steps;
    const float scale = 1.4142135381698608f * sqrtf(dt);   // sqrt2 * sqrt_dt
    const uint32_t one = umin((uint32_t)steps, 1u);        // opaque 1 for IMAD

    float x0 = xin[3 * i + 0];
    float x1 = xin[3 * i + 1];
    float x2 = xin[3 * i + 2];

    const uint32_t base = 3u * (uint32_t)i;

    for (int s = 0; s < steps; ++s) {
        const StepKey k = g_step_keys[s];

        // three fresh signed random words for this (point, step)
        const uint32_t c1k = base + k.a.y;   // counter + k1, shared init
        int32_t b0 = tf_sbits(k, c1k,      one);
        int32_t b1 = tf_sbits(k, c1k + 1u, one);
        int32_t b2 = tf_sbits(k, c1k + 2u, one);

        float v0 = normal_from_sbits(b0, scale);
        float v1 = normal_from_sbits(b1, scale);
        float v2 = normal_from_sbits(b2, scale);

        // Closed-form Heun step on the sphere (||x|| == 1):
        //   a = x.v, q' = v.v - a^2
        //   r1 = (a + q') / (1 + q')
        //   z  = alpha*x + beta*v,  beta = 1 - r1/2,
        //   alpha = beta - 0.5*a*(1 - r1)
        float a  = dot3(x0, x1, x2, v0, v1, v2);
        float q  = dot3(v0, v1, v2, v0, v1, v2);
        float qp = fmaf(-a, a, q);
        float r1 = (a + qp) * rcp_fast(1.0f + qp);
        float beta  = fmaf(-0.5f, r1, 1.0f);
        float t     = 1.0f - r1;
        float alpha = fmaf(-0.5f, a * t, beta);

        float z0 = fmaf(beta, v0, alpha * x0);
        float z1 = fmaf(beta, v1, alpha * x1);
        float z2 = fmaf(beta, v2, alpha * x2);

        float inv = rsqrt_fast(dot3(z0, z1, z2, z0, z1, z2));
        x0 = z0 * inv;
        x1 = z1 * inv;
        x2 = z2 * inv;
    }

    out[3 * i + 0] = x0;
    out[3 * i + 1] = x1;
    out[3 * i + 2] = x2;
}

// ---------------------------------------------------------------------------
extern "C" void kernel_launch(void* const* d_in, const int* in_sizes, int n_in,
                              void* d_out, int out_size) {
    const float* x     = (const float*)d_in[0];
    const int*   t     = (const int*)d_in[1];
    const int*   steps = (const int*)d_in[2];
    const int n = in_sizes[0] / 3;

    keys_kernel<<<1, 256>>>(steps);

    const int threads = 256;
    const int blocks = (n + threads - 1) / threads;
    sbm_kernel<<<blocks, threads>>>(x, t, steps, (float*)d_out, n);
}